// round 3
// baseline (speedup 1.0000x reference)
#include <cuda_runtime.h>
#include <cstdint>

// Problem constants: B=4, N=256, H=8, D=8, HD=64
#define BB   4
#define NN   256
#define HH   8
#define HD   64
#define BN   (BB*NN)     // 1024

// Device scratch (no allocations allowed)
__device__ float g_Q[BN * HD];
__device__ float g_K[BN * HD];               // pre-scaled by D^-0.5
__device__ float g_V[BN * HD];
__device__ float g_qk[BN * NN * HH];         // qk[b,i,j,h]  8MB, L2-resident

// ---------------------------------------------------------------------------
// Kernel A: Q/K/V projections. 128 blocks x 192 threads, 8 rows per block.
// W staged in smem once per block. out[row,c] = sum_k h[row,k]*W[c,k]
// ---------------------------------------------------------------------------
__global__ __launch_bounds__(192) void proj_kernel(
    const float* __restrict__ h,
    const float* __restrict__ Wq,
    const float* __restrict__ Wk,
    const float* __restrict__ Wv)
{
    __shared__ float Wsh[3 * HD * HD];   // 48KB
    int tid = threadIdx.x;

    for (int idx = tid; idx < 3 * 1024; idx += 192) {
        float4 val;
        if (idx < 1024)      val = reinterpret_cast<const float4*>(Wq)[idx];
        else if (idx < 2048) val = reinterpret_cast<const float4*>(Wk)[idx - 1024];
        else                 val = reinterpret_cast<const float4*>(Wv)[idx - 2048];
        reinterpret_cast<float4*>(Wsh)[idx] = val;
    }
    __syncthreads();

    int mat = tid / HD;            // 0=Q, 1=K, 2=V
    int c   = tid % HD;
    const float4* Wr = reinterpret_cast<const float4*>(Wsh + mat * 4096 + c * HD);
    float scale = (mat == 1) ? 0.35355339059327373f : 1.0f;
    float* dst = (mat == 0) ? g_Q : (mat == 1) ? g_K : g_V;

    int row0 = blockIdx.x * 8;
#pragma unroll
    for (int r = 0; r < 8; r++) {
        int row = row0 + r;
        const float4* hv = reinterpret_cast<const float4*>(h + row * HD);
        float acc = 0.f;
#pragma unroll
        for (int k = 0; k < 16; k++) {
            int kk = (k + c) & 15;           // skew to avoid bank conflicts
            float4 w = Wr[kk];
            float4 x = hv[kk];
            acc += w.x * x.x + w.y * x.y + w.z * x.z + w.w * x.w;
        }
        dst[row * HD + c] = acc * scale;
    }
}

// ---------------------------------------------------------------------------
// Kernel B: qk scores. qk[b,i,j,h] = Q[b,i,h,:] . K[b,j,h,:]  (K pre-scaled)
// 128 blocks x 256 threads; warp = one i (8 i per block), lane strides j by 32.
// K stays L2-hot (256KB total; 8MB L2 reads chip-wide).
// ---------------------------------------------------------------------------
__global__ __launch_bounds__(256) void qk_kernel()
{
    int b    = blockIdx.x >> 5;
    int i    = ((blockIdx.x & 31) << 3) + (threadIdx.x >> 5);
    int lane = threadIdx.x & 31;

    const float4* Qr = reinterpret_cast<const float4*>(g_Q + ((b << 8) + i) * HD);
    float4 q[16];
#pragma unroll
    for (int k = 0; k < 16; k++) q[k] = Qr[k];

    float* dst = g_qk + (((size_t)(b << 8) + i) * NN) * HH;

#pragma unroll 2
    for (int jt = 0; jt < 8; jt++) {
        int j = (jt << 5) + lane;
        const float4* Kr = reinterpret_cast<const float4*>(g_K + ((b << 8) + j) * HD);
        float4 o[2];
#pragma unroll
        for (int hh = 0; hh < HH; hh++) {
            float4 ka = Kr[2 * hh], kb = Kr[2 * hh + 1];
            float4 qa = q[2 * hh],  qb = q[2 * hh + 1];
            float acc = ka.x * qa.x + ka.y * qa.y + ka.z * qa.z + ka.w * qa.w
                      + kb.x * qb.x + kb.y * qb.y + kb.z * qb.z + kb.w * qb.w;
            ((float*)o)[hh] = acc;
        }
        reinterpret_cast<float4*>(dst + j * HH)[0] = o[0];
        reinterpret_cast<float4*>(dst + j * HH)[1] = o[1];
    }
}

// ---------------------------------------------------------------------------
// Kernel C: fused attention streaming. One block (128 thr) per (b,i).
// Single resident wave (1024 blocks, 8 blocks/SM). Lane owns 2 channels,
// warp w strides j by 4. No smem pipeline; __ldcs streams e_att/e_value.
// ---------------------------------------------------------------------------
__global__ __launch_bounds__(128, 8) void attn_kernel(
    const float* __restrict__ e_att,
    const float* __restrict__ e_value,
    const float* __restrict__ mask,
    float* __restrict__ out)
{
    int bi   = blockIdx.x;
    int b    = bi >> 8;
    int i    = bi & 255;
    int tid  = threadIdx.x;
    int lane = tid & 31;
    int w    = tid >> 5;
    int hh   = lane >> 2;          // head of channels (2*lane, 2*lane+1)

    __shared__ float red[4][32][4];

    const float2* ea2 = reinterpret_cast<const float2*>(e_att)   + (size_t)bi * NN * 32;
    const float2* ev2 = reinterpret_cast<const float2*>(e_value) + (size_t)bi * NN * 32;
    const float2* v2  = reinterpret_cast<const float2*>(g_V)     + (size_t)b  * NN * 32;
    const float*  qkp = g_qk + (size_t)bi * NN * HH;
    const float*  mp  = mask + b * NN;
    float mi = __ldg(mp + i);

    float ax = 0.f, ay = 0.f, dx = 0.f, dy = 0.f;

#pragma unroll 4
    for (int j = w; j < NN; j += 4) {
        float2 ea = __ldcs(&ea2[j * 32 + lane]);
        float2 ev = __ldcs(&ev2[j * 32 + lane]);
        float2 v  = __ldg (&v2 [j * 32 + lane]);
        float  qk = __ldg (&qkp[j * HH + hh]);
        float  m  = mi * __ldg(mp + j);

        float sx = __expf(fminf(fmaxf(qk + ea.x, -5.f), 5.f)) * m;
        float sy = __expf(fminf(fmaxf(qk + ea.y, -5.f), 5.f)) * m;
        dx += sx; dy += sy;
        ax += sx * m * (v.x + ev.x);
        ay += sy * m * (v.y + ev.y);
    }

    red[w][lane][0] = ax; red[w][lane][1] = ay;
    red[w][lane][2] = dx; red[w][lane][3] = dy;
    __syncthreads();

    if (tid < 32) {
        float a0 = 0.f, a1 = 0.f, d0 = 0.f, d1 = 0.f;
#pragma unroll
        for (int ww = 0; ww < 4; ww++) {
            a0 += red[ww][tid][0]; a1 += red[ww][tid][1];
            d0 += red[ww][tid][2]; d1 += red[ww][tid][3];
        }
        float2 o;
        o.x = a0 / fmaxf(d0, 1e-6f);
        o.y = a1 / fmaxf(d1, 1e-6f);
        reinterpret_cast<float2*>(out + (size_t)bi * HD)[tid] = o;
    }
}

// ---------------------------------------------------------------------------
extern "C" void kernel_launch(void* const* d_in, const int* in_sizes, int n_in,
                              void* d_out, int out_size)
{
    const float* h       = (const float*)d_in[0];
    const float* e_att   = (const float*)d_in[1];
    const float* e_value = (const float*)d_in[2];
    const float* mask    = (const float*)d_in[3];
    const float* Wq      = (const float*)d_in[4];
    const float* Wk      = (const float*)d_in[5];
    const float* Wv      = (const float*)d_in[6];
    float* out           = (float*)d_out;

    proj_kernel<<<BN / 8, 192>>>(h, Wq, Wk, Wv);
    qk_kernel<<<128, 256>>>();
    attn_kernel<<<BN, 128>>>(e_att, e_value, mask, out);
}

// round 4
// speedup vs baseline: 1.6146x; 1.6146x over previous
#include <cuda_runtime.h>
#include <cstdint>

// Problem constants: B=4, N=256, H=8, D=8, HD=64
#define BB   4
#define NN   256
#define HH   8
#define HD   64
#define BN   (BB*NN)     // 1024
#define TJ   16          // j per tile
#define ST   2           // pipeline stages
#define SJ   2           // j-split factor (blocks per row)
#define TPB  8           // tiles per block = (NN/TJ)/SJ
#define JH   (NN/SJ)     // 128 j per block
#define TILE_F (TJ*HD)   // 1024 floats
#define TILE_B (TILE_F*4)// 4096 bytes

// Device scratch (no allocations allowed)
__device__ float g_Q[BN * HD];
__device__ float g_K[BN * HD];                  // pre-scaled by D^-0.5
__device__ float g_V[BN * HD];
__device__ float g_part[BN * SJ * 2 * HD];      // [bi][half][acc64|den64]  1MB

// ---------------------------------------------------------------------------
// PTX helpers
// ---------------------------------------------------------------------------
__device__ __forceinline__ uint32_t s2u(const void* p) {
    return (uint32_t)__cvta_generic_to_shared(p);
}
__device__ __forceinline__ void mbar_init(uint32_t mbar, uint32_t count) {
    asm volatile("mbarrier.init.shared::cta.b64 [%0], %1;" :: "r"(mbar), "r"(count) : "memory");
}
__device__ __forceinline__ void mbar_expect_tx(uint32_t mbar, uint32_t bytes) {
    asm volatile("mbarrier.arrive.expect_tx.shared::cta.b64 _, [%0], %1;"
                 :: "r"(mbar), "r"(bytes) : "memory");
}
__device__ __forceinline__ void mbar_wait(uint32_t mbar, uint32_t parity) {
    uint32_t done = 0;
    while (!done) {
        asm volatile("{\n\t.reg .pred p;\n\t"
                     "mbarrier.try_wait.parity.acquire.cta.shared::cta.b64 p, [%1], %2, 0x989680;\n\t"
                     "selp.b32 %0, 1, 0, p;\n\t}"
                     : "=r"(done) : "r"(mbar), "r"(parity) : "memory");
    }
}
__device__ __forceinline__ void bulk_g2s(uint32_t dst, const void* src, uint32_t bytes, uint32_t mbar) {
    asm volatile("cp.async.bulk.shared::cluster.global.mbarrier::complete_tx::bytes "
                 "[%0], [%1], %2, [%3];"
                 :: "r"(dst), "l"(src), "r"(bytes), "r"(mbar) : "memory");
}
__device__ __forceinline__ void fence_async_proxy() {
    asm volatile("fence.proxy.async.shared::cta;" ::: "memory");
}

// ---------------------------------------------------------------------------
// Kernel A: Q/K/V projections. 256 blocks x 192 threads, 4 rows per block.
// ---------------------------------------------------------------------------
__global__ __launch_bounds__(192) void proj_kernel(
    const float* __restrict__ h,
    const float* __restrict__ Wq,
    const float* __restrict__ Wk,
    const float* __restrict__ Wv)
{
    __shared__ float Wsh[3 * HD * HD];   // 48KB
    int tid = threadIdx.x;

    for (int idx = tid; idx < 3 * 1024; idx += 192) {
        float4 val;
        if (idx < 1024)      val = reinterpret_cast<const float4*>(Wq)[idx];
        else if (idx < 2048) val = reinterpret_cast<const float4*>(Wk)[idx - 1024];
        else                 val = reinterpret_cast<const float4*>(Wv)[idx - 2048];
        reinterpret_cast<float4*>(Wsh)[idx] = val;
    }
    __syncthreads();

    int mat = tid / HD;            // 0=Q, 1=K, 2=V
    int c   = tid % HD;
    const float4* Wr = reinterpret_cast<const float4*>(Wsh + mat * 4096 + c * HD);
    float scale = (mat == 1) ? 0.35355339059327373f : 1.0f;
    float* dst = (mat == 0) ? g_Q : (mat == 1) ? g_K : g_V;

    int row0 = blockIdx.x * 4;
#pragma unroll
    for (int r = 0; r < 4; r++) {
        int row = row0 + r;
        const float4* hv = reinterpret_cast<const float4*>(h + row * HD);
        float acc = 0.f;
#pragma unroll
        for (int k = 0; k < 16; k++) {
            int kk = (k + c) & 15;           // skew to spread smem banks
            float4 w = Wr[kk];
            float4 x = __ldg(&hv[kk]);
            acc += w.x * x.x + w.y * x.y + w.z * x.z + w.w * x.w;
        }
        dst[row * HD + c] = acc * scale;
    }
}

// ---------------------------------------------------------------------------
// Kernel B: fused attention, TMA-pipelined, j split in halves.
// Block g: bi = g>>1, half = g&1, j in [half*128, half*128+128), 8 tiles.
// 256 threads: tid = jg*16 + cg. Thread handles j = j0 + t*16 + jg,
// channels 4cg..4cg+3. qk held in 8 registers (computed from L2-hot g_K).
// Partial acc/den written to g_part (no divide).
// ---------------------------------------------------------------------------
__global__ __launch_bounds__(256, 5) void attn_kernel(
    const float* __restrict__ e_att,
    const float* __restrict__ e_value,
    const float* __restrict__ mask)
{
    int g   = blockIdx.x;          // 0..2047
    int bi  = g >> 1;
    int shf = g & 1;
    int b   = bi >> 8;
    int i   = bi & 255;
    int tid = threadIdx.x;
    int cg  = tid & 15;
    int jg  = tid >> 4;
    int hh  = cg >> 1;
    int j0  = shf * JH;

    __shared__ __align__(128) float ea_t[ST][TILE_F];
    __shared__ __align__(128) float ev_t[ST][TILE_F];
    __shared__ __align__(128) float v_t [ST][TILE_F];
    __shared__ float m_sh[JH];
    __shared__ float red[8][16][8];
    __shared__ __align__(8) unsigned long long mbar[ST];

    uint32_t mb0 = s2u(&mbar[0]);
    const char* ea_g = reinterpret_cast<const char*>(e_att)   + ((size_t)bi * NN + j0) * HD * 4;
    const char* ev_g = reinterpret_cast<const char*>(e_value) + ((size_t)bi * NN + j0) * HD * 4;
    const char* v_g  = reinterpret_cast<const char*>(g_V)     + ((size_t)b  * NN + j0) * HD * 4;

    if (tid == 0) {
        mbar_init(mb0, 1);
        mbar_init(mb0 + 8, 1);
        fence_async_proxy();
#pragma unroll
        for (int t = 0; t < ST; t++) {
            uint32_t mb = mb0 + t * 8;
            mbar_expect_tx(mb, 3 * TILE_B);
            bulk_g2s(s2u(&ea_t[t][0]), ea_g + (size_t)t * TILE_B, TILE_B, mb);
            bulk_g2s(s2u(&ev_t[t][0]), ev_g + (size_t)t * TILE_B, TILE_B, mb);
            bulk_g2s(s2u(&v_t [t][0]), v_g  + (size_t)t * TILE_B, TILE_B, mb);
        }
    }

    if (tid < JH) m_sh[tid] = mask[b * NN + j0 + tid];
    float mi = __ldg(mask + b * NN + i);

    // qk in registers: qk[t] = Q[b,i,hh,:] . K[b,j0+t*16+jg,hh,:]
    float qk[TPB];
    {
        const float4* Qh = reinterpret_cast<const float4*>(g_Q + bi * HD + hh * 8);
        float4 qa = Qh[0], qb = Qh[1];
#pragma unroll
        for (int t = 0; t < TPB; t++) {
            int j = j0 + t * TJ + jg;
            const float4* Kh = reinterpret_cast<const float4*>(g_K + ((b << 8) + j) * HD + hh * 8);
            float4 ka = Kh[0], kb = Kh[1];
            qk[t] = ka.x * qa.x + ka.y * qa.y + ka.z * qa.z + ka.w * qa.w
                  + kb.x * qb.x + kb.y * qb.y + kb.z * qb.z + kb.w * qb.w;
        }
    }
    __syncthreads();   // mbar init + m_sh visible

    float4 acc = make_float4(0.f, 0.f, 0.f, 0.f);
    float4 den = make_float4(0.f, 0.f, 0.f, 0.f);

#pragma unroll
    for (int t = 0; t < TPB; t++) {
        int s = t & (ST - 1);
        uint32_t mb = mb0 + s * 8;
        mbar_wait(mb, (t >> 1) & 1);

        float4 ea = reinterpret_cast<const float4*>(ea_t[s])[tid];
        float4 ev = reinterpret_cast<const float4*>(ev_t[s])[tid];
        float4 v  = reinterpret_cast<const float4*>(v_t [s])[tid];
        float  m  = mi * m_sh[t * TJ + jg];
        float  q  = qk[t];

        float s0x = __expf(fminf(fmaxf(q + ea.x, -5.f), 5.f));
        float s0y = __expf(fminf(fmaxf(q + ea.y, -5.f), 5.f));
        float s0z = __expf(fminf(fmaxf(q + ea.z, -5.f), 5.f));
        float s0w = __expf(fminf(fmaxf(q + ea.w, -5.f), 5.f));

        float smx = s0x * m, smy = s0y * m, smz = s0z * m, smw = s0w * m;
        den.x += smx; den.y += smy; den.z += smz; den.w += smw;
        acc.x += smx * m * (v.x + ev.x);
        acc.y += smy * m * (v.y + ev.y);
        acc.z += smz * m * (v.z + ev.z);
        acc.w += smw * m * (v.w + ev.w);

        __syncthreads();   // stage s fully consumed

        if (tid == 0 && t + ST < TPB) {
            int tn = t + ST;
            mbar_expect_tx(mb, 3 * TILE_B);
            bulk_g2s(s2u(&ea_t[s][0]), ea_g + (size_t)tn * TILE_B, TILE_B, mb);
            bulk_g2s(s2u(&ev_t[s][0]), ev_g + (size_t)tn * TILE_B, TILE_B, mb);
            bulk_g2s(s2u(&v_t [s][0]), v_g  + (size_t)tn * TILE_B, TILE_B, mb);
        }
    }

    // reduce jg-pair within warp (lanes L and L^16 share cg)
    acc.x += __shfl_xor_sync(0xffffffffu, acc.x, 16);
    acc.y += __shfl_xor_sync(0xffffffffu, acc.y, 16);
    acc.z += __shfl_xor_sync(0xffffffffu, acc.z, 16);
    acc.w += __shfl_xor_sync(0xffffffffu, acc.w, 16);
    den.x += __shfl_xor_sync(0xffffffffu, den.x, 16);
    den.y += __shfl_xor_sync(0xffffffffu, den.y, 16);
    den.z += __shfl_xor_sync(0xffffffffu, den.z, 16);
    den.w += __shfl_xor_sync(0xffffffffu, den.w, 16);

    if ((tid & 16) == 0) {
        int w = tid >> 5;
        float* r = &red[w][cg][0];
        r[0] = acc.x; r[1] = acc.y; r[2] = acc.z; r[3] = acc.w;
        r[4] = den.x; r[5] = den.y; r[6] = den.z; r[7] = den.w;
    }
    __syncthreads();

    if (tid < HD) {
        int c   = tid;
        int cgr = c >> 2;
        int k   = c & 3;
        float a = 0.f, d = 0.f;
#pragma unroll
        for (int w = 0; w < 8; w++) {
            a += red[w][cgr][k];
            d += red[w][cgr][4 + k];
        }
        g_part[(size_t)g * 2 * HD + c]      = a;
        g_part[(size_t)g * 2 * HD + HD + c] = d;
    }
}

// ---------------------------------------------------------------------------
// Kernel C: finalize. Sum the SJ halves, divide, write out.
// ---------------------------------------------------------------------------
__global__ __launch_bounds__(256) void fin_kernel(float* __restrict__ out)
{
    int idx = blockIdx.x * 256 + threadIdx.x;   // 0..65535
    int bi  = idx >> 6;
    int c   = idx & 63;
    const float* p0 = g_part + (size_t)(bi * 2)     * 2 * HD;
    const float* p1 = g_part + (size_t)(bi * 2 + 1) * 2 * HD;
    float a = p0[c] + p1[c];
    float d = p0[HD + c] + p1[HD + c];
    out[idx] = a / fmaxf(d, 1e-6f);
}

// ---------------------------------------------------------------------------
extern "C" void kernel_launch(void* const* d_in, const int* in_sizes, int n_in,
                              void* d_out, int out_size)
{
    const float* h       = (const float*)d_in[0];
    const float* e_att   = (const float*)d_in[1];
    const float* e_value = (const float*)d_in[2];
    const float* mask    = (const float*)d_in[3];
    const float* Wq      = (const float*)d_in[4];
    const float* Wk      = (const float*)d_in[5];
    const float* Wv      = (const float*)d_in[6];
    float* out           = (float*)d_out;

    proj_kernel<<<BN / 4, 192>>>(h, Wq, Wk, Wv);
    attn_kernel<<<BN * SJ, 256>>>(e_att, e_value, mask);
    fin_kernel<<<BN * HD / 256, 256>>>(out);
}

// round 5
// speedup vs baseline: 1.8003x; 1.1150x over previous
#include <cuda_runtime.h>
#include <cstdint>

// Problem constants: B=4, N=256, H=8, D=8, HD=64
#define BB   4
#define NN   256
#define HH   8
#define HD   64
#define BN   (BB*NN)     // 1024
#define TJ   16          // j per tile
#define ST   2           // pipeline stages
#define SJ   2           // j-split factor (blocks per row)
#define TPB  8           // tiles per block = (NN/TJ)/SJ
#define JH   (NN/SJ)     // 128 j per block
#define TILE_F (TJ*HD)   // 1024 floats
#define TILE_B (TILE_F*4)// 4096 bytes

// Device scratch (no allocations allowed)
__device__ float g_Q[BN * HD];
__device__ float g_K[BN * HD];                  // pre-scaled by D^-0.5
__device__ float g_V[BN * HD];
__device__ float g_part[BN * SJ * 2 * HD];      // [bi][half][acc64|den64]  1MB

// ---------------------------------------------------------------------------
// PTX helpers
// ---------------------------------------------------------------------------
__device__ __forceinline__ uint32_t s2u(const void* p) {
    return (uint32_t)__cvta_generic_to_shared(p);
}
__device__ __forceinline__ void mbar_init(uint32_t mbar, uint32_t count) {
    asm volatile("mbarrier.init.shared::cta.b64 [%0], %1;" :: "r"(mbar), "r"(count) : "memory");
}
__device__ __forceinline__ void mbar_expect_tx(uint32_t mbar, uint32_t bytes) {
    asm volatile("mbarrier.arrive.expect_tx.shared::cta.b64 _, [%0], %1;"
                 :: "r"(mbar), "r"(bytes) : "memory");
}
__device__ __forceinline__ void mbar_wait(uint32_t mbar, uint32_t parity) {
    uint32_t done = 0;
    while (!done) {
        asm volatile("{\n\t.reg .pred p;\n\t"
                     "mbarrier.try_wait.parity.acquire.cta.shared::cta.b64 p, [%1], %2, 0x989680;\n\t"
                     "selp.b32 %0, 1, 0, p;\n\t}"
                     : "=r"(done) : "r"(mbar), "r"(parity) : "memory");
    }
}
__device__ __forceinline__ void bulk_g2s(uint32_t dst, const void* src, uint32_t bytes, uint32_t mbar) {
    asm volatile("cp.async.bulk.shared::cluster.global.mbarrier::complete_tx::bytes "
                 "[%0], [%1], %2, [%3];"
                 :: "r"(dst), "l"(src), "r"(bytes), "r"(mbar) : "memory");
}
__device__ __forceinline__ void fence_async_proxy() {
    asm volatile("fence.proxy.async.shared::cta;" ::: "memory");
}

// ---------------------------------------------------------------------------
// Kernel A: Q/K/V projections, latency-lean.
// grid 128 x 192 threads. Block handles 8 rows; only h rows staged in smem
// (2KB). Warp w -> (mat = w%3, row-quad = w/3). Lane owns cols {l, l+32}
// x 4 rows = 8 independent accumulators. W read from global (L1/L2-hot).
// ---------------------------------------------------------------------------
__global__ __launch_bounds__(192) void proj_kernel(
    const float* __restrict__ h,
    const float* __restrict__ Wq,
    const float* __restrict__ Wk,
    const float* __restrict__ Wv)
{
    __shared__ float hs[8 * HD];        // 2KB: 8 rows of h
    int tid  = threadIdx.x;
    int row0 = blockIdx.x * 8;

    if (tid < 128)
        reinterpret_cast<float4*>(hs)[tid] =
            reinterpret_cast<const float4*>(h + row0 * HD)[tid];
    __syncthreads();

    int w      = tid >> 5;              // warp 0..5
    int lane   = tid & 31;
    int mat    = w % 3;                 // 0=Q, 1=K, 2=V
    int rquad  = w / 3;                 // 0 or 1 -> rows rquad*4 .. +3
    int c0     = lane;
    int c1     = lane + 32;

    const float* W = (mat == 0) ? Wq : (mat == 1) ? Wk : Wv;
    const float4* W0 = reinterpret_cast<const float4*>(W + c0 * HD);
    const float4* W1 = reinterpret_cast<const float4*>(W + c1 * HD);
    float scale = (mat == 1) ? 0.35355339059327373f : 1.0f;
    float* dst  = (mat == 0) ? g_Q : (mat == 1) ? g_K : g_V;

    float a0[4] = {0.f, 0.f, 0.f, 0.f};
    float a1[4] = {0.f, 0.f, 0.f, 0.f};

#pragma unroll
    for (int kt = 0; kt < 16; kt++) {
        float4 w0 = __ldg(&W0[kt]);
        float4 w1 = __ldg(&W1[kt]);
#pragma unroll
        for (int r = 0; r < 4; r++) {
            float4 x = reinterpret_cast<const float4*>(hs + (rquad * 4 + r) * HD)[kt];
            a0[r] += w0.x * x.x + w0.y * x.y + w0.z * x.z + w0.w * x.w;
            a1[r] += w1.x * x.x + w1.y * x.y + w1.z * x.z + w1.w * x.w;
        }
    }

#pragma unroll
    for (int r = 0; r < 4; r++) {
        int row = row0 + rquad * 4 + r;
        dst[row * HD + c0] = a0[r] * scale;
        dst[row * HD + c1] = a1[r] * scale;
    }
}

// ---------------------------------------------------------------------------
// Kernel B: fused attention, TMA-pipelined, j split in halves. (unchanged)
// ---------------------------------------------------------------------------
__global__ __launch_bounds__(256, 5) void attn_kernel(
    const float* __restrict__ e_att,
    const float* __restrict__ e_value,
    const float* __restrict__ mask)
{
    int g   = blockIdx.x;          // 0..2047
    int bi  = g >> 1;
    int shf = g & 1;
    int b   = bi >> 8;
    int i   = bi & 255;
    int tid = threadIdx.x;
    int cg  = tid & 15;
    int jg  = tid >> 4;
    int hh  = cg >> 1;
    int j0  = shf * JH;

    __shared__ __align__(128) float ea_t[ST][TILE_F];
    __shared__ __align__(128) float ev_t[ST][TILE_F];
    __shared__ __align__(128) float v_t [ST][TILE_F];
    __shared__ float m_sh[JH];
    __shared__ float red[8][16][8];
    __shared__ __align__(8) unsigned long long mbar[ST];

    uint32_t mb0 = s2u(&mbar[0]);
    const char* ea_g = reinterpret_cast<const char*>(e_att)   + ((size_t)bi * NN + j0) * HD * 4;
    const char* ev_g = reinterpret_cast<const char*>(e_value) + ((size_t)bi * NN + j0) * HD * 4;
    const char* v_g  = reinterpret_cast<const char*>(g_V)     + ((size_t)b  * NN + j0) * HD * 4;

    if (tid == 0) {
        mbar_init(mb0, 1);
        mbar_init(mb0 + 8, 1);
        fence_async_proxy();
#pragma unroll
        for (int t = 0; t < ST; t++) {
            uint32_t mb = mb0 + t * 8;
            mbar_expect_tx(mb, 3 * TILE_B);
            bulk_g2s(s2u(&ea_t[t][0]), ea_g + (size_t)t * TILE_B, TILE_B, mb);
            bulk_g2s(s2u(&ev_t[t][0]), ev_g + (size_t)t * TILE_B, TILE_B, mb);
            bulk_g2s(s2u(&v_t [t][0]), v_g  + (size_t)t * TILE_B, TILE_B, mb);
        }
    }

    if (tid < JH) m_sh[tid] = mask[b * NN + j0 + tid];
    float mi = __ldg(mask + b * NN + i);

    // qk in registers: qk[t] = Q[b,i,hh,:] . K[b,j0+t*16+jg,hh,:]
    float qk[TPB];
    {
        const float4* Qh = reinterpret_cast<const float4*>(g_Q + bi * HD + hh * 8);
        float4 qa = Qh[0], qb = Qh[1];
#pragma unroll
        for (int t = 0; t < TPB; t++) {
            int j = j0 + t * TJ + jg;
            const float4* Kh = reinterpret_cast<const float4*>(g_K + ((b << 8) + j) * HD + hh * 8);
            float4 ka = Kh[0], kb = Kh[1];
            qk[t] = ka.x * qa.x + ka.y * qa.y + ka.z * qa.z + ka.w * qa.w
                  + kb.x * qb.x + kb.y * qb.y + kb.z * qb.z + kb.w * qb.w;
        }
    }
    __syncthreads();   // mbar init + m_sh visible

    float4 acc = make_float4(0.f, 0.f, 0.f, 0.f);
    float4 den = make_float4(0.f, 0.f, 0.f, 0.f);

#pragma unroll
    for (int t = 0; t < TPB; t++) {
        int s = t & (ST - 1);
        uint32_t mb = mb0 + s * 8;
        mbar_wait(mb, (t >> 1) & 1);

        float4 ea = reinterpret_cast<const float4*>(ea_t[s])[tid];
        float4 ev = reinterpret_cast<const float4*>(ev_t[s])[tid];
        float4 v  = reinterpret_cast<const float4*>(v_t [s])[tid];
        float  m  = mi * m_sh[t * TJ + jg];
        float  q  = qk[t];

        float s0x = __expf(fminf(fmaxf(q + ea.x, -5.f), 5.f));
        float s0y = __expf(fminf(fmaxf(q + ea.y, -5.f), 5.f));
        float s0z = __expf(fminf(fmaxf(q + ea.z, -5.f), 5.f));
        float s0w = __expf(fminf(fmaxf(q + ea.w, -5.f), 5.f));

        float smx = s0x * m, smy = s0y * m, smz = s0z * m, smw = s0w * m;
        den.x += smx; den.y += smy; den.z += smz; den.w += smw;
        acc.x += smx * m * (v.x + ev.x);
        acc.y += smy * m * (v.y + ev.y);
        acc.z += smz * m * (v.z + ev.z);
        acc.w += smw * m * (v.w + ev.w);

        __syncthreads();   // stage s fully consumed

        if (tid == 0 && t + ST < TPB) {
            int tn = t + ST;
            mbar_expect_tx(mb, 3 * TILE_B);
            bulk_g2s(s2u(&ea_t[s][0]), ea_g + (size_t)tn * TILE_B, TILE_B, mb);
            bulk_g2s(s2u(&ev_t[s][0]), ev_g + (size_t)tn * TILE_B, TILE_B, mb);
            bulk_g2s(s2u(&v_t [s][0]), v_g  + (size_t)tn * TILE_B, TILE_B, mb);
        }
    }

    // reduce jg-pair within warp (lanes L and L^16 share cg)
    acc.x += __shfl_xor_sync(0xffffffffu, acc.x, 16);
    acc.y += __shfl_xor_sync(0xffffffffu, acc.y, 16);
    acc.z += __shfl_xor_sync(0xffffffffu, acc.z, 16);
    acc.w += __shfl_xor_sync(0xffffffffu, acc.w, 16);
    den.x += __shfl_xor_sync(0xffffffffu, den.x, 16);
    den.y += __shfl_xor_sync(0xffffffffu, den.y, 16);
    den.z += __shfl_xor_sync(0xffffffffu, den.z, 16);
    den.w += __shfl_xor_sync(0xffffffffu, den.w, 16);

    if ((tid & 16) == 0) {
        int w = tid >> 5;
        float* r = &red[w][cg][0];
        r[0] = acc.x; r[1] = acc.y; r[2] = acc.z; r[3] = acc.w;
        r[4] = den.x; r[5] = den.y; r[6] = den.z; r[7] = den.w;
    }
    __syncthreads();

    if (tid < HD) {
        int c   = tid;
        int cgr = c >> 2;
        int k   = c & 3;
        float a = 0.f, d = 0.f;
#pragma unroll
        for (int w = 0; w < 8; w++) {
            a += red[w][cgr][k];
            d += red[w][cgr][4 + k];
        }
        g_part[(size_t)g * 2 * HD + c]      = a;
        g_part[(size_t)g * 2 * HD + HD + c] = d;
    }
}

// ---------------------------------------------------------------------------
// Kernel C: finalize. Sum the SJ halves, divide, write out.
// ---------------------------------------------------------------------------
__global__ __launch_bounds__(256) void fin_kernel(float* __restrict__ out)
{
    int idx = blockIdx.x * 256 + threadIdx.x;   // 0..65535
    int bi  = idx >> 6;
    int c   = idx & 63;
    const float* p0 = g_part + (size_t)(bi * 2)     * 2 * HD;
    const float* p1 = g_part + (size_t)(bi * 2 + 1) * 2 * HD;
    float a = p0[c] + p1[c];
    float d = p0[HD + c] + p1[HD + c];
    out[idx] = a / fmaxf(d, 1e-6f);
}

// ---------------------------------------------------------------------------
extern "C" void kernel_launch(void* const* d_in, const int* in_sizes, int n_in,
                              void* d_out, int out_size)
{
    const float* h       = (const float*)d_in[0];
    const float* e_att   = (const float*)d_in[1];
    const float* e_value = (const float*)d_in[2];
    const float* mask    = (const float*)d_in[3];
    const float* Wq      = (const float*)d_in[4];
    const float* Wk      = (const float*)d_in[5];
    const float* Wv      = (const float*)d_in[6];
    float* out           = (float*)d_out;

    proj_kernel<<<128, 192>>>(h, Wq, Wk, Wv);
    attn_kernel<<<BN * SJ, 256>>>(e_att, e_value, mask);
    fin_kernel<<<BN * HD / 256, 256>>>(out);
}

// round 6
// speedup vs baseline: 1.8695x; 1.0384x over previous
#include <cuda_runtime.h>
#include <cstdint>

// Problem constants: B=4, N=256, H=8, D=8, HD=64
#define BB   4
#define NN   256
#define HH   8
#define HD   64
#define BN   (BB*NN)     // 1024
#define TJ   16          // j per tile
#define ST   2           // pipeline stages
#define SJ   2           // j-split factor (blocks per row)
#define TPB  8           // tiles per block = (NN/TJ)/SJ
#define JH   (NN/SJ)     // 128 j per block
#define TILE_F (TJ*HD)   // 1024 floats
#define TILE_B (TILE_F*4)// 4096 bytes

// Device scratch (no allocations allowed)
__device__ float g_Q[BN * HD];
__device__ float g_K[BN * HD];                  // pre-scaled by D^-0.5
__device__ float g_V[BN * HD];
__device__ float g_part[BN * SJ * 2 * HD];      // [bi][half][acc64|den64]  1MB

// ---------------------------------------------------------------------------
// PTX helpers
// ---------------------------------------------------------------------------
__device__ __forceinline__ uint32_t s2u(const void* p) {
    return (uint32_t)__cvta_generic_to_shared(p);
}
__device__ __forceinline__ void mbar_init(uint32_t mbar, uint32_t count) {
    asm volatile("mbarrier.init.shared::cta.b64 [%0], %1;" :: "r"(mbar), "r"(count) : "memory");
}
__device__ __forceinline__ void mbar_expect_tx(uint32_t mbar, uint32_t bytes) {
    asm volatile("mbarrier.arrive.expect_tx.shared::cta.b64 _, [%0], %1;"
                 :: "r"(mbar), "r"(bytes) : "memory");
}
__device__ __forceinline__ void mbar_wait(uint32_t mbar, uint32_t parity) {
    uint32_t done = 0;
    while (!done) {
        asm volatile("{\n\t.reg .pred p;\n\t"
                     "mbarrier.try_wait.parity.acquire.cta.shared::cta.b64 p, [%1], %2, 0x989680;\n\t"
                     "selp.b32 %0, 1, 0, p;\n\t}"
                     : "=r"(done) : "r"(mbar), "r"(parity) : "memory");
    }
}
__device__ __forceinline__ void bulk_g2s(uint32_t dst, const void* src, uint32_t bytes, uint32_t mbar) {
    asm volatile("cp.async.bulk.shared::cluster.global.mbarrier::complete_tx::bytes "
                 "[%0], [%1], %2, [%3];"
                 :: "r"(dst), "l"(src), "r"(bytes), "r"(mbar) : "memory");
}
__device__ __forceinline__ void fence_async_proxy() {
    asm volatile("fence.proxy.async.shared::cta;" ::: "memory");
}

// ---------------------------------------------------------------------------
// Kernel A: Q/K/V projections, broadcast-W / transposed-h scheme.
// grid = 32 row-groups x 6 combo-groups = 192 blocks, 256 threads.
// combo = mat*64 + c  (192 combos); combo-group cgp covers [cgp*32, cgp*32+32).
// Warp w owns 4 combos; lane = row within the 32-row group.
// hsT[k][row] (pad 33) -> conflict-free LDS; W loads warp-uniform (broadcast).
// Output bounced through smem for coalesced global stores.
// ---------------------------------------------------------------------------
__global__ __launch_bounds__(256) void proj_kernel(
    const float* __restrict__ h,
    const float* __restrict__ Wq,
    const float* __restrict__ Wk,
    const float* __restrict__ Wv)
{
    __shared__ float hsT[HD * 33];      // transposed h: hsT[k*33 + r], 8.4KB
    __shared__ float osh[32 * 33];      // output bounce: osh[r*33 + cmb], 4.2KB

    int tid  = threadIdx.x;
    int rg   = blockIdx.x >> 602 % 1;   // placeholder avoided
    rg       = blockIdx.x / 6;          // row group 0..31
    int cgp  = blockIdx.x % 6;          // combo group 0..5
    int row0 = rg * 32;

    // Stage 32 rows of h, transposed. Global reads coalesced (lane -> k).
#pragma unroll
    for (int p = 0; p < 8; p++) {
        int idx = p * 256 + tid;        // 0..2047
        int r   = idx >> 6;             // local row
        int k   = idx & 63;
        hsT[k * 33 + r] = h[(row0 + r) * HD + k];
    }
    __syncthreads();

    int w    = tid >> 5;                // warp 0..7
    int lane = tid & 31;                // = local row
    int cmb0 = cgp * 32 + w * 4;        // first of 4 combos for this warp
    int mat  = cmb0 >> 6;               // all 4 combos share mat (32 | 64)
    int cb   = cmb0 & 63;

    const float* W = (mat == 0) ? Wq : (mat == 1) ? Wk : Wv;
    const float4* Wr0 = reinterpret_cast<const float4*>(W + (cb + 0) * HD);
    const float4* Wr1 = reinterpret_cast<const float4*>(W + (cb + 1) * HD);
    const float4* Wr2 = reinterpret_cast<const float4*>(W + (cb + 2) * HD);
    const float4* Wr3 = reinterpret_cast<const float4*>(W + (cb + 3) * HD);
    float scale = (mat == 1) ? 0.35355339059327373f : 1.0f;

    float a0 = 0.f, a1 = 0.f, a2 = 0.f, a3 = 0.f;
#pragma unroll
    for (int kt = 0; kt < 16; kt++) {
        float4 w0 = __ldg(&Wr0[kt]);    // warp-uniform -> broadcast
        float4 w1 = __ldg(&Wr1[kt]);
        float4 w2 = __ldg(&Wr2[kt]);
        float4 w3 = __ldg(&Wr3[kt]);
        float x0 = hsT[(kt * 4 + 0) * 33 + lane];
        float x1 = hsT[(kt * 4 + 1) * 33 + lane];
        float x2 = hsT[(kt * 4 + 2) * 33 + lane];
        float x3 = hsT[(kt * 4 + 3) * 33 + lane];
        a0 += w0.x * x0 + w0.y * x1 + w0.z * x2 + w0.w * x3;
        a1 += w1.x * x0 + w1.y * x1 + w1.z * x2 + w1.w * x3;
        a2 += w2.x * x0 + w2.y * x1 + w2.z * x2 + w2.w * x3;
        a3 += w3.x * x0 + w3.y * x1 + w3.z * x2 + w3.w * x3;
    }

    int cl = w * 4;                     // local combo base
    osh[lane * 33 + cl + 0] = a0 * scale;
    osh[lane * 33 + cl + 1] = a1 * scale;
    osh[lane * 33 + cl + 2] = a2 * scale;
    osh[lane * 33 + cl + 3] = a3 * scale;
    __syncthreads();

    // Coalesced store: warp lanes -> consecutive c for a fixed row.
    float* dst = (cgp < 2) ? g_Q : (cgp < 4) ? g_K : g_V;
    int cbase  = (cgp & 1) * 32;
#pragma unroll
    for (int p = 0; p < 4; p++) {
        int r   = (tid >> 5) + p * 8;   // local row 0..31
        int cmb = tid & 31;
        dst[(row0 + r) * HD + cbase + cmb] = osh[r * 33 + cmb];
    }
}

// ---------------------------------------------------------------------------
// Kernel B: fused attention, TMA-pipelined, j split in halves. (unchanged)
// ---------------------------------------------------------------------------
__global__ __launch_bounds__(256, 5) void attn_kernel(
    const float* __restrict__ e_att,
    const float* __restrict__ e_value,
    const float* __restrict__ mask)
{
    int g   = blockIdx.x;          // 0..2047
    int bi  = g >> 1;
    int shf = g & 1;
    int b   = bi >> 8;
    int i   = bi & 255;
    int tid = threadIdx.x;
    int cg  = tid & 15;
    int jg  = tid >> 4;
    int hh  = cg >> 1;
    int j0  = shf * JH;

    __shared__ __align__(128) float ea_t[ST][TILE_F];
    __shared__ __align__(128) float ev_t[ST][TILE_F];
    __shared__ __align__(128) float v_t [ST][TILE_F];
    __shared__ float m_sh[JH];
    __shared__ float red[8][16][8];
    __shared__ __align__(8) unsigned long long mbar[ST];

    uint32_t mb0 = s2u(&mbar[0]);
    const char* ea_g = reinterpret_cast<const char*>(e_att)   + ((size_t)bi * NN + j0) * HD * 4;
    const char* ev_g = reinterpret_cast<const char*>(e_value) + ((size_t)bi * NN + j0) * HD * 4;
    const char* v_g  = reinterpret_cast<const char*>(g_V)     + ((size_t)b  * NN + j0) * HD * 4;

    if (tid == 0) {
        mbar_init(mb0, 1);
        mbar_init(mb0 + 8, 1);
        fence_async_proxy();
#pragma unroll
        for (int t = 0; t < ST; t++) {
            uint32_t mb = mb0 + t * 8;
            mbar_expect_tx(mb, 3 * TILE_B);
            bulk_g2s(s2u(&ea_t[t][0]), ea_g + (size_t)t * TILE_B, TILE_B, mb);
            bulk_g2s(s2u(&ev_t[t][0]), ev_g + (size_t)t * TILE_B, TILE_B, mb);
            bulk_g2s(s2u(&v_t [t][0]), v_g  + (size_t)t * TILE_B, TILE_B, mb);
        }
    }

    if (tid < JH) m_sh[tid] = mask[b * NN + j0 + tid];
    float mi = __ldg(mask + b * NN + i);

    // qk in registers: qk[t] = Q[b,i,hh,:] . K[b,j0+t*16+jg,hh,:]
    float qk[TPB];
    {
        const float4* Qh = reinterpret_cast<const float4*>(g_Q + bi * HD + hh * 8);
        float4 qa = Qh[0], qb = Qh[1];
#pragma unroll
        for (int t = 0; t < TPB; t++) {
            int j = j0 + t * TJ + jg;
            const float4* Kh = reinterpret_cast<const float4*>(g_K + ((b << 8) + j) * HD + hh * 8);
            float4 ka = Kh[0], kb = Kh[1];
            qk[t] = ka.x * qa.x + ka.y * qa.y + ka.z * qa.z + ka.w * qa.w
                  + kb.x * qb.x + kb.y * qb.y + kb.z * qb.z + kb.w * qb.w;
        }
    }
    __syncthreads();   // mbar init + m_sh visible

    float4 acc = make_float4(0.f, 0.f, 0.f, 0.f);
    float4 den = make_float4(0.f, 0.f, 0.f, 0.f);

#pragma unroll
    for (int t = 0; t < TPB; t++) {
        int s = t & (ST - 1);
        uint32_t mb = mb0 + s * 8;
        mbar_wait(mb, (t >> 1) & 1);

        float4 ea = reinterpret_cast<const float4*>(ea_t[s])[tid];
        float4 ev = reinterpret_cast<const float4*>(ev_t[s])[tid];
        float4 v  = reinterpret_cast<const float4*>(v_t [s])[tid];
        float  m  = mi * m_sh[t * TJ + jg];
        float  q  = qk[t];

        float s0x = __expf(fminf(fmaxf(q + ea.x, -5.f), 5.f));
        float s0y = __expf(fminf(fmaxf(q + ea.y, -5.f), 5.f));
        float s0z = __expf(fminf(fmaxf(q + ea.z, -5.f), 5.f));
        float s0w = __expf(fminf(fmaxf(q + ea.w, -5.f), 5.f));

        float smx = s0x * m, smy = s0y * m, smz = s0z * m, smw = s0w * m;
        den.x += smx; den.y += smy; den.z += smz; den.w += smw;
        acc.x += smx * m * (v.x + ev.x);
        acc.y += smy * m * (v.y + ev.y);
        acc.z += smz * m * (v.z + ev.z);
        acc.w += smw * m * (v.w + ev.w);

        __syncthreads();   // stage s fully consumed

        if (tid == 0 && t + ST < TPB) {
            int tn = t + ST;
            mbar_expect_tx(mb, 3 * TILE_B);
            bulk_g2s(s2u(&ea_t[s][0]), ea_g + (size_t)tn * TILE_B, TILE_B, mb);
            bulk_g2s(s2u(&ev_t[s][0]), ev_g + (size_t)tn * TILE_B, TILE_B, mb);
            bulk_g2s(s2u(&v_t [s][0]), v_g  + (size_t)tn * TILE_B, TILE_B, mb);
        }
    }

    // reduce jg-pair within warp (lanes L and L^16 share cg)
    acc.x += __shfl_xor_sync(0xffffffffu, acc.x, 16);
    acc.y += __shfl_xor_sync(0xffffffffu, acc.y, 16);
    acc.z += __shfl_xor_sync(0xffffffffu, acc.z, 16);
    acc.w += __shfl_xor_sync(0xffffffffu, acc.w, 16);
    den.x += __shfl_xor_sync(0xffffffffu, den.x, 16);
    den.y += __shfl_xor_sync(0xffffffffu, den.y, 16);
    den.z += __shfl_xor_sync(0xffffffffu, den.z, 16);
    den.w += __shfl_xor_sync(0xffffffffu, den.w, 16);

    if ((tid & 16) == 0) {
        int w = tid >> 5;
        float* r = &red[w][cg][0];
        r[0] = acc.x; r[1] = acc.y; r[2] = acc.z; r[3] = acc.w;
        r[4] = den.x; r[5] = den.y; r[6] = den.z; r[7] = den.w;
    }
    __syncthreads();

    if (tid < HD) {
        int c   = tid;
        int cgr = c >> 2;
        int k   = c & 3;
        float a = 0.f, d = 0.f;
#pragma unroll
        for (int w = 0; w < 8; w++) {
            a += red[w][cgr][k];
            d += red[w][cgr][4 + k];
        }
        g_part[(size_t)g * 2 * HD + c]      = a;
        g_part[(size_t)g * 2 * HD + HD + c] = d;
    }
}

// ---------------------------------------------------------------------------
// Kernel C: finalize. Sum the SJ halves, divide, write out.
// ---------------------------------------------------------------------------
__global__ __launch_bounds__(256) void fin_kernel(float* __restrict__ out)
{
    int idx = blockIdx.x * 256 + threadIdx.x;   // 0..65535
    int bi  = idx >> 6;
    int c   = idx & 63;
    const float* p0 = g_part + (size_t)(bi * 2)     * 2 * HD;
    const float* p1 = g_part + (size_t)(bi * 2 + 1) * 2 * HD;
    float a = p0[c] + p1[c];
    float d = p0[HD + c] + p1[HD + c];
    out[idx] = a / fmaxf(d, 1e-6f);
}

// ---------------------------------------------------------------------------
extern "C" void kernel_launch(void* const* d_in, const int* in_sizes, int n_in,
                              void* d_out, int out_size)
{
    const float* h       = (const float*)d_in[0];
    const float* e_att   = (const float*)d_in[1];
    const float* e_value = (const float*)d_in[2];
    const float* mask    = (const float*)d_in[3];
    const float* Wq      = (const float*)d_in[4];
    const float* Wk      = (const float*)d_in[5];
    const float* Wv      = (const float*)d_in[6];
    float* out           = (float*)d_out;

    proj_kernel<<<192, 256>>>(h, Wq, Wk, Wv);
    attn_kernel<<<BN * SJ, 256>>>(e_att, e_value, mask);
    fin_kernel<<<BN * HD / 256, 256>>>(out);
}